// round 1
// baseline (speedup 1.0000x reference)
#include <cuda_runtime.h>
#include <math.h>

#define BB   512
#define FREQ 8
#define EE   1024
#define HH   8
#define HD   128
#define DIN  3072
#define LROWS 4096
#define SEQ  512
#define NH   64

__device__ float g_z[LROWS * EE];
__device__ float g_qkv[LROWS * 3 * EE];
__device__ float g_scores[NH * SEQ * SEQ];
__device__ float g_attn_o[LROWS * EE];
__device__ float g_zrec[LROWS * EE];

template<bool TB>
__global__ __launch_bounds__(256)
void gemm_kernel(const float* __restrict__ A, int lda, long long sA1, long long sA2,
                 const float* __restrict__ Bm, int ldb, long long sB1, long long sB2,
                 const float* __restrict__ bias,
                 float* __restrict__ C, int ldc, long long sC1, long long sC2,
                 int M, int N, int K, float alpha, int bdiv)
{
    __shared__ float As[8][128];
    __shared__ float Bs[8][128];

    const int bz = blockIdx.z;
    const int n = bz / bdiv, h = bz % bdiv;
    A  += n * sA1 + h * sA2;
    Bm += n * sB1 + h * sB2;
    C  += n * sC1 + h * sC2;

    const int rowBase = blockIdx.y * 128;
    const int colBase = blockIdx.x * 128;
    const int tid = threadIdx.x;
    const int ty = tid >> 4, tx = tid & 15;

    const int arow = tid >> 1;
    const int ak   = (tid & 1) * 4;
    const float* Aptr = A + (long long)(rowBase + arow) * lda + ak;

    const float* Bptr;
    int bcol = 0, bk = 0, bkr = 0, bc = 0;
    if (TB) {
        bcol = tid >> 1; bk = (tid & 1) * 4;
        Bptr = Bm + (long long)(colBase + bcol) * ldb + bk;
    } else {
        bkr = tid >> 5; bc = (tid & 31) * 4;
        Bptr = Bm + (long long)bkr * ldb + colBase + bc;
    }

    float acc[8][8];
#pragma unroll
    for (int i = 0; i < 8; i++)
#pragma unroll
        for (int j = 0; j < 8; j++) acc[i][j] = 0.0f;

    for (int k0 = 0; k0 < K; k0 += 8) {
        float4 av = *(const float4*)(Aptr + k0);
        As[ak + 0][arow] = av.x;
        As[ak + 1][arow] = av.y;
        As[ak + 2][arow] = av.z;
        As[ak + 3][arow] = av.w;

        if (TB) {
            float4 bv = *(const float4*)(Bptr + k0);
            Bs[bk + 0][bcol] = bv.x;
            Bs[bk + 1][bcol] = bv.y;
            Bs[bk + 2][bcol] = bv.z;
            Bs[bk + 3][bcol] = bv.w;
        } else {
            float4 bv = *(const float4*)(Bptr + (long long)k0 * ldb);
            *(float4*)&Bs[bkr][bc] = bv;
        }
        __syncthreads();

#pragma unroll
        for (int kk = 0; kk < 8; kk++) {
            float a[8], b[8];
            *(float4*)(a)     = *(const float4*)&As[kk][ty * 8];
            *(float4*)(a + 4) = *(const float4*)&As[kk][ty * 8 + 4];
            *(float4*)(b)     = *(const float4*)&Bs[kk][tx * 8];
            *(float4*)(b + 4) = *(const float4*)&Bs[kk][tx * 8 + 4];
#pragma unroll
            for (int i = 0; i < 8; i++)
#pragma unroll
                for (int j = 0; j < 8; j++)
                    acc[i][j] = fmaf(a[i], b[j], acc[i][j]);
        }
        __syncthreads();
    }

#pragma unroll
    for (int i = 0; i < 8; i++) {
        const int row = rowBase + ty * 8 + i;
#pragma unroll
        for (int j = 0; j < 8; j += 4) {
            const int col = colBase + tx * 8 + j;
            float4 v;
            v.x = acc[i][j + 0] * alpha;
            v.y = acc[i][j + 1] * alpha;
            v.z = acc[i][j + 2] * alpha;
            v.w = acc[i][j + 3] * alpha;
            if (bias) {
                v.x += bias[col + 0];
                v.y += bias[col + 1];
                v.z += bias[col + 2];
                v.w += bias[col + 3];
            }
            *(float4*)(C + (long long)row * ldc + col) = v;
        }
    }
}

__global__ __launch_bounds__(256)
void softmax512(float* __restrict__ S)
{
    float* p = S + (long long)blockIdx.x * 512;
    const int t = threadIdx.x;
    const float a = p[t];
    const float b = p[t + 256];

    float m = fmaxf(a, b);
#pragma unroll
    for (int o = 16; o; o >>= 1) m = fmaxf(m, __shfl_xor_sync(0xFFFFFFFFu, m, o));
    __shared__ float sm[8];
    if ((t & 31) == 0) sm[t >> 5] = m;
    __syncthreads();
    float mm = sm[0];
#pragma unroll
    for (int i = 1; i < 8; i++) mm = fmaxf(mm, sm[i]);

    const float e0 = __expf(a - mm);
    const float e1 = __expf(b - mm);
    float s = e0 + e1;
#pragma unroll
    for (int o = 16; o; o >>= 1) s += __shfl_xor_sync(0xFFFFFFFFu, s, o);
    __shared__ float ss[8];
    if ((t & 31) == 0) ss[t >> 5] = s;
    __syncthreads();
    float tot = 0.0f;
#pragma unroll
    for (int i = 0; i < 8; i++) tot += ss[i];
    const float inv = 1.0f / tot;
    p[t] = e0 * inv;
    p[t + 256] = e1 * inv;
}

__global__ __launch_bounds__(256)
void pred_kernel(const float* __restrict__ xrec, float* __restrict__ xpred)
{
    const int idx = blockIdx.x * blockDim.x + threadIdx.x;
    const int c4 = idx & 15;
    const int t  = (idx >> 4) % 192;
    const int b  = idx / (16 * 192);
    const int s  = t % 48;
    const float4 v = *(const float4*)(xrec + (long long)b * 24576 + 7 * 3072 + s * 64 + c4 * 4);
    ((float4*)xpred)[idx] = v;
}

extern "C" void kernel_launch(void* const* d_in, const int* in_sizes, int n_in,
                              void* d_out, int out_size)
{
    const float* x        = (const float*)d_in[0];
    const float* enc_W    = (const float*)d_in[1];
    const float* enc_b    = (const float*)d_in[2];
    const float* dec_W    = (const float*)d_in[3];
    const float* dec_b    = (const float*)d_in[4];
    const float* in_projW = (const float*)d_in[5];
    const float* in_projb = (const float*)d_in[6];
    const float* out_W    = (const float*)d_in[7];
    const float* out_b    = (const float*)d_in[8];
    float* out = (float*)d_out;

    float *z, *qkv, *scores, *attn_o, *zrec;
    cudaGetSymbolAddress((void**)&z,      g_z);
    cudaGetSymbolAddress((void**)&qkv,    g_qkv);
    cudaGetSymbolAddress((void**)&scores, g_scores);
    cudaGetSymbolAddress((void**)&attn_o, g_attn_o);
    cudaGetSymbolAddress((void**)&zrec,   g_zrec);

    const float att_scale = 1.0f / sqrtf((float)HD);
    const long long QKV_L = 3LL * EE;         // row stride of qkv (per (l,n) row)
    const long long LDQKV = 3LL * EE * FREQ;  // stride between consecutive l (fixed n)

    // 1) z = x @ enc_W + enc_b
    gemm_kernel<false><<<dim3(EE / 128, LROWS / 128, 1), 256>>>(
        x, DIN, 0, 0, enc_W, EE, 0, 0, enc_b,
        z, EE, 0, 0, LROWS, EE, DIN, 1.0f, 1);

    // 2) qkv = z @ in_proj_W^T + in_proj_b
    gemm_kernel<true><<<dim3(3 * EE / 128, LROWS / 128, 1), 256>>>(
        z, EE, 0, 0, in_projW, EE, 0, 0, in_projb,
        qkv, 3 * EE, 0, 0, LROWS, 3 * EE, EE, 1.0f, 1);

    // 3) scores[n,h] = alpha * Q @ K^T   (strided views, batch = n*8+h)
    gemm_kernel<true><<<dim3(SEQ / 128, SEQ / 128, NH), 256>>>(
        qkv,      (int)LDQKV, QKV_L, HD,
        qkv + EE, (int)LDQKV, QKV_L, HD,
        nullptr,
        scores, SEQ, (long long)HH * SEQ * SEQ, (long long)SEQ * SEQ,
        SEQ, SEQ, HD, att_scale, HH);

    // 4) softmax
    softmax512<<<NH * SEQ, 256>>>(scores);

    // 5) attn_o[(l*8+n)*1024 + h*128 + d] = sum_m P[n,h,l,m] * V[m,n,h,d]
    gemm_kernel<false><<<dim3(HD / 128, SEQ / 128, NH), 256>>>(
        scores, SEQ, (long long)HH * SEQ * SEQ, (long long)SEQ * SEQ,
        qkv + 2 * EE, (int)LDQKV, QKV_L, HD,
        nullptr,
        attn_o, FREQ * EE, EE, HD,
        SEQ, HD, SEQ, 1.0f, HH);

    // 6) z_rec = attn_o @ out_W^T + out_b
    gemm_kernel<true><<<dim3(EE / 128, LROWS / 128, 1), 256>>>(
        attn_o, EE, 0, 0, out_W, EE, 0, 0, out_b,
        zrec, EE, 0, 0, LROWS, EE, EE, 1.0f, 1);

    // 7) x_rec = z_rec @ dec_W + dec_b  (contiguous -> straight into d_out)
    gemm_kernel<false><<<dim3(DIN / 128, LROWS / 128, 1), 256>>>(
        zrec, EE, 0, 0, dec_W, DIN, 0, 0, dec_b,
        out, DIN, 0, 0, LROWS, DIN, EE, 1.0f, 1);

    // 8) x_pred = tile of last chunk of x_rec
    pred_kernel<<<(BB * 192 * 64 / 4) / 256, 256>>>(out, out + (long long)BB * 384 * 64);
}

// round 3
// speedup vs baseline: 2.9314x; 2.9314x over previous
#include <cuda_runtime.h>
#include <math.h>

#define BB   512
#define FREQ 8
#define EE   1024
#define HH   8
#define HD   128
#define DIN  3072
#define LROWS 4096
#define SEQ  512
#define NH   64

__device__ float g_z[LROWS * EE];
__device__ float g_qkv[LROWS * 3 * EE];
__device__ float g_scores[NH * SEQ * SEQ];
__device__ float g_attn_o[LROWS * EE];
__device__ float g_zrec[LROWS * EE];

#define AS_STRIDE 20        // 16 k + 4 pad (words)
#define BS_KN_STRIDE 136    // 128 n + 8 pad (words)

__device__ __forceinline__ unsigned f2tf(float f) {
    unsigned u;
    asm("cvt.rna.tf32.f32 %0, %1;" : "=r"(u) : "f"(f));
    return u;
}

__device__ __forceinline__ unsigned smem_u32(const void* p) {
    unsigned a;
    asm("{ .reg .u64 t; cvta.to.shared.u64 t, %1; cvt.u32.u64 %0, t; }"
        : "=r"(a) : "l"(p));
    return a;
}

__device__ __forceinline__ void cp16(unsigned dst, const void* src) {
    asm volatile("cp.async.cg.shared.global [%0], [%1], 16;" :: "r"(dst), "l"(src));
}

__device__ __forceinline__ void mma_tf32(float c[4], const unsigned a[4], const unsigned b[2]) {
    asm volatile(
        "mma.sync.aligned.m16n8k8.row.col.f32.tf32.tf32.f32 "
        "{%0,%1,%2,%3}, {%4,%5,%6,%7}, {%8,%9}, {%0,%1,%2,%3};\n"
        : "+f"(c[0]), "+f"(c[1]), "+f"(c[2]), "+f"(c[3])
        : "r"(a[0]), "r"(a[1]), "r"(a[2]), "r"(a[3]), "r"(b[0]), "r"(b[1]));
}

// C = alpha * A @ (TB ? B^T : B) + bias, batched/strided.
// A: [M,K] row-major (lda). TB: B [N,K] row-major; !TB: B [K,N] row-major.
// Tile: 128x128 per CTA, K-step 16, 8 warps of 64x32, double-buffered cp.async.
template<bool TB>
__global__ __launch_bounds__(256, 1)
void gemm_tc(const float* __restrict__ A, long long lda, long long sA1, long long sA2,
             const float* __restrict__ Bm, long long ldb, long long sB1, long long sB2,
             const float* __restrict__ bias,
             float* __restrict__ C, long long ldc, long long sC1, long long sC2,
             int K, float alpha, int bdiv)
{
    constexpr int BS_WORDS = TB ? (128 * AS_STRIDE) : (16 * BS_KN_STRIDE);
    __shared__ float As[2][128 * AS_STRIDE];
    __shared__ float Bs[2][BS_WORDS];

    const int bz = blockIdx.z;
    const int n_b = bz / bdiv, h_b = bz % bdiv;
    A  += n_b * sA1 + h_b * sA2;
    Bm += n_b * sB1 + h_b * sB2;
    C  += n_b * sC1 + h_b * sC2;

    const int rowBase = blockIdx.y * 128;
    const int colBase = blockIdx.x * 128;
    const int tid  = threadIdx.x;
    const int wid  = tid >> 5;
    const int lane = tid & 31;
    const int warpM = wid >> 2;      // 0..1
    const int warpN = wid & 3;       // 0..3
    const int gid = lane >> 2;       // 0..7
    const int tig = lane & 3;        // 0..3

    // ---- async load helpers (computed once) ----
    const int arow = tid >> 1;
    const int ak4  = (tid & 1) * 8;
    const float* aSrcBase = A + (long long)(rowBase + arow) * lda + ak4;
    const unsigned aDst0 = smem_u32(&As[0][arow * AS_STRIDE + ak4]);
    const unsigned aDst1 = smem_u32(&As[1][arow * AS_STRIDE + ak4]);

    const float* bSrcBase;
    unsigned bDst0, bDst1;
    long long bSrcStep2 = 0;     // second chunk offset (floats) for NN
    if (TB) {
        const int brow = tid >> 1;
        const int bk4  = (tid & 1) * 8;
        bSrcBase = Bm + (long long)(colBase + brow) * ldb + bk4;
        bDst0 = smem_u32(&Bs[0][brow * AS_STRIDE + bk4]);
        bDst1 = smem_u32(&Bs[1][brow * AS_STRIDE + bk4]);
    } else {
        const int bkr = tid >> 5;          // 0..7 (also bkr+8)
        const int bn4 = (tid & 31) * 4;
        bSrcBase = Bm + (long long)bkr * ldb + colBase + bn4;
        bSrcStep2 = 8LL * ldb;
        bDst0 = smem_u32(&Bs[0][bkr * BS_KN_STRIDE + bn4]);
        bDst1 = smem_u32(&Bs[1][bkr * BS_KN_STRIDE + bn4]);
    }

    float acc[4][4][4];
#pragma unroll
    for (int i = 0; i < 4; i++)
#pragma unroll
        for (int j = 0; j < 4; j++)
#pragma unroll
            for (int r = 0; r < 4; r++) acc[i][j][r] = 0.0f;

    const int KT = K >> 4;

    // issue stage 0
    {
        cp16(aDst0, aSrcBase);
        cp16(aDst0 + 16, aSrcBase + 4);
        if (TB) {
            cp16(bDst0, bSrcBase);
            cp16(bDst0 + 16, bSrcBase + 4);
        } else {
            cp16(bDst0, bSrcBase);
            cp16(bDst0 + 8 * BS_KN_STRIDE * 4, bSrcBase + bSrcStep2);
        }
        asm volatile("cp.async.commit_group;" ::: "memory");
    }

    for (int kt = 0; kt < KT; kt++) {
        if (kt + 1 < KT) {
            const int k0 = (kt + 1) << 4;
            const unsigned ad = ((kt + 1) & 1) ? aDst1 : aDst0;
            const unsigned bd = ((kt + 1) & 1) ? bDst1 : bDst0;
            cp16(ad, aSrcBase + k0);
            cp16(ad + 16, aSrcBase + k0 + 4);
            if (TB) {
                cp16(bd, bSrcBase + k0);
                cp16(bd + 16, bSrcBase + k0 + 4);
            } else {
                const float* bs = bSrcBase + (long long)k0 * ldb;
                cp16(bd, bs);
                cp16(bd + 8 * BS_KN_STRIDE * 4, bs + bSrcStep2);
            }
            asm volatile("cp.async.commit_group;" ::: "memory");
            asm volatile("cp.async.wait_group 1;" ::: "memory");
        } else {
            asm volatile("cp.async.wait_group 0;" ::: "memory");
        }
        __syncthreads();

        const float* as = As[kt & 1];
        const float* bs = Bs[kt & 1];

#pragma unroll
        for (int ks = 0; ks < 16; ks += 8) {
            unsigned afr[4][4];
#pragma unroll
            for (int mt = 0; mt < 4; mt++) {
                const int r = warpM * 64 + mt * 16 + gid;
                afr[mt][0] = f2tf(as[r * AS_STRIDE + ks + tig]);
                afr[mt][1] = f2tf(as[(r + 8) * AS_STRIDE + ks + tig]);
                afr[mt][2] = f2tf(as[r * AS_STRIDE + ks + tig + 4]);
                afr[mt][3] = f2tf(as[(r + 8) * AS_STRIDE + ks + tig + 4]);
            }
            unsigned bfr[4][2];
#pragma unroll
            for (int nt = 0; nt < 4; nt++) {
                const int n = warpN * 32 + nt * 8 + gid;
                if (TB) {
                    bfr[nt][0] = f2tf(bs[n * AS_STRIDE + ks + tig]);
                    bfr[nt][1] = f2tf(bs[n * AS_STRIDE + ks + tig + 4]);
                } else {
                    bfr[nt][0] = f2tf(bs[(ks + tig) * BS_KN_STRIDE + n]);
                    bfr[nt][1] = f2tf(bs[(ks + tig + 4) * BS_KN_STRIDE + n]);
                }
            }
#pragma unroll
            for (int mt = 0; mt < 4; mt++)
#pragma unroll
                for (int nt = 0; nt < 4; nt++)
                    mma_tf32(acc[mt][nt], afr[mt], bfr[nt]);
        }
        __syncthreads();
    }

    // epilogue
#pragma unroll
    for (int mt = 0; mt < 4; mt++) {
        const int r0 = rowBase + warpM * 64 + mt * 16 + gid;
#pragma unroll
        for (int nt = 0; nt < 4; nt++) {
            const int c0 = colBase + warpN * 32 + nt * 8 + tig * 2;
            float b0 = 0.0f, b1 = 0.0f;
            if (bias) { b0 = bias[c0]; b1 = bias[c0 + 1]; }
            float2 v0, v1;
            v0.x = acc[mt][nt][0] * alpha + b0;
            v0.y = acc[mt][nt][1] * alpha + b1;
            v1.x = acc[mt][nt][2] * alpha + b0;
            v1.y = acc[mt][nt][3] * alpha + b1;
            *(float2*)(C + (long long)r0 * ldc + c0) = v0;
            *(float2*)(C + (long long)(r0 + 8) * ldc + c0) = v1;
        }
    }
}

__global__ __launch_bounds__(256)
void softmax512(float* __restrict__ S)
{
    float* p = S + (long long)blockIdx.x * 512;
    const int t = threadIdx.x;
    const float a = p[t];
    const float b = p[t + 256];

    float m = fmaxf(a, b);
#pragma unroll
    for (int o = 16; o; o >>= 1) m = fmaxf(m, __shfl_xor_sync(0xFFFFFFFFu, m, o));
    __shared__ float sm[8];
    if ((t & 31) == 0) sm[t >> 5] = m;
    __syncthreads();
    float mm = sm[0];
#pragma unroll
    for (int i = 1; i < 8; i++) mm = fmaxf(mm, sm[i]);

    const float e0 = __expf(a - mm);
    const float e1 = __expf(b - mm);
    float s = e0 + e1;
#pragma unroll
    for (int o = 16; o; o >>= 1) s += __shfl_xor_sync(0xFFFFFFFFu, s, o);
    __shared__ float ss[8];
    if ((t & 31) == 0) ss[t >> 5] = s;
    __syncthreads();
    float tot = 0.0f;
#pragma unroll
    for (int i = 0; i < 8; i++) tot += ss[i];
    const float inv = 1.0f / tot;
    p[t] = e0 * inv;
    p[t + 256] = e1 * inv;
}

__global__ __launch_bounds__(256)
void pred_kernel(const float* __restrict__ xrec, float* __restrict__ xpred)
{
    const int idx = blockIdx.x * blockDim.x + threadIdx.x;
    const int c4 = idx & 15;
    const int t  = (idx >> 4) % 192;
    const int b  = idx / (16 * 192);
    const int s  = t % 48;
    const float4 v = *(const float4*)(xrec + (long long)b * 24576 + 7 * 3072 + s * 64 + c4 * 4);
    ((float4*)xpred)[idx] = v;
}

extern "C" void kernel_launch(void* const* d_in, const int* in_sizes, int n_in,
                              void* d_out, int out_size)
{
    const float* x        = (const float*)d_in[0];
    const float* enc_W    = (const float*)d_in[1];
    const float* enc_b    = (const float*)d_in[2];
    const float* dec_W    = (const float*)d_in[3];
    const float* dec_b    = (const float*)d_in[4];
    const float* in_projW = (const float*)d_in[5];
    const float* in_projb = (const float*)d_in[6];
    const float* out_W    = (const float*)d_in[7];
    const float* out_b    = (const float*)d_in[8];
    float* out = (float*)d_out;

    float *z, *qkv, *scores, *attn_o, *zrec;
    cudaGetSymbolAddress((void**)&z,      g_z);
    cudaGetSymbolAddress((void**)&qkv,    g_qkv);
    cudaGetSymbolAddress((void**)&scores, g_scores);
    cudaGetSymbolAddress((void**)&attn_o, g_attn_o);
    cudaGetSymbolAddress((void**)&zrec,   g_zrec);

    const float att_scale = 1.0f / sqrtf((float)HD);
    const long long QKV_L = 3LL * EE;         // qkv row stride per (l,n) row
    const long long LDQKV = 3LL * EE * FREQ;  // stride between consecutive l (fixed n)

    // 1) z = x @ enc_W + enc_b                       (NN, 4096x1024x3072)
    gemm_tc<false><<<dim3(EE / 128, LROWS / 128, 1), 256>>>(
        x, DIN, 0, 0, enc_W, EE, 0, 0, enc_b,
        z, EE, 0, 0, DIN, 1.0f, 1);

    // 2) qkv = z @ in_proj_W^T + in_proj_b           (NT, 4096x3072x1024)
    gemm_tc<true><<<dim3(3 * EE / 128, LROWS / 128, 1), 256>>>(
        z, EE, 0, 0, in_projW, EE, 0, 0, in_projb,
        qkv, 3 * EE, 0, 0, EE, 1.0f, 1);

    // 3) scores[n,h] = alpha * Q @ K^T               (NT batched, 64 x 512x512x128)
    gemm_tc<true><<<dim3(SEQ / 128, SEQ / 128, NH), 256>>>(
        qkv,      LDQKV, QKV_L, HD,
        qkv + EE, LDQKV, QKV_L, HD,
        nullptr,
        scores, SEQ, (long long)HH * SEQ * SEQ, (long long)SEQ * SEQ,
        HD, att_scale, HH);

    // 4) softmax
    softmax512<<<NH * SEQ, 256>>>(scores);

    // 5) attn_o = P @ V (written into (L,N,E) layout) (NN batched, 64 x 512x128x512)
    gemm_tc<false><<<dim3(HD / 128, SEQ / 128, NH), 256>>>(
        scores, SEQ, (long long)HH * SEQ * SEQ, (long long)SEQ * SEQ,
        qkv + 2 * EE, LDQKV, QKV_L, HD,
        nullptr,
        attn_o, (long long)FREQ * EE, EE, HD,
        SEQ, 1.0f, HH);

    // 6) z_rec = attn_o @ out_W^T + out_b            (NT, 4096x1024x1024)
    gemm_tc<true><<<dim3(EE / 128, LROWS / 128, 1), 256>>>(
        attn_o, EE, 0, 0, out_W, EE, 0, 0, out_b,
        zrec, EE, 0, 0, EE, 1.0f, 1);

    // 7) x_rec = z_rec @ dec_W + dec_b -> d_out      (NN, 4096x3072x1024)
    gemm_tc<false><<<dim3(DIN / 128, LROWS / 128, 1), 256>>>(
        zrec, EE, 0, 0, dec_W, DIN, 0, 0, dec_b,
        out, DIN, 0, 0, EE, 1.0f, 1);

    // 8) x_pred = tile of last chunk of x_rec
    pred_kernel<<<(BB * 192 * 64 / 4) / 256, 256>>>(out, out + (long long)BB * 384 * 64);
}